// round 7
// baseline (speedup 1.0000x reference)
#include <cuda_runtime.h>
#include <math.h>
#include <stdint.h>

// ---------------------------------------------------------------------------
// CompletionNet via warp-level tf32 mma.sync + cp.async smem gather ring.
// - Activations pre-rounded to tf32 by producer (cvt pass / fused in bnelu):
//   conv hot loop has zero cvt instructions.
// - Physical ci permutation (ci = tg*8 + kt*2 + h): each lane's A-fragment
//   bytes are contiguous 32B spans of a row.
// - Gather pipelined 2 offsets ahead via cp.async.cg into a per-warp 3-stage
//   smem ring (zfill for idx<0). Lane reads back only its own bytes -> no
//   block/warp syncs in the main loop; cp.async.wait_group is sufficient.
// - Warp tile M=16 (block tile 128 voxels), 3 blocks/SM.
// - BN stats fused into conv epilogue.
// ---------------------------------------------------------------------------

#define NMAX 500000
#define EPS  1e-5f
#define STAGES 3
#define ROWPITCH 144                       // bytes; conflict-free LDS.128
#define WSTAGE (16 * ROWPITCH)             // 2304 B per warp per stage
#define RING_BYTES (8 * STAGES * WSTAGE)   // 55296 B per block

__device__ float g_bufA[NMAX * 32];
__device__ float g_bufB[NMAX * 32];
__device__ float g_bufC[NMAX * 32];
__device__ float g_stats[3 * 64];    // per layer: sum[32], sumsq[32]
__device__ float g_Wp[62 * 1024];    // per k: 256 float4 fragment pairs

typedef unsigned int u32;

__device__ __forceinline__ u32 tf32_rna(float x) {
    u32 y; asm("cvt.rna.tf32.f32 %0, %1;" : "=r"(y) : "f"(x)); return y;
}
__device__ __forceinline__ u32 smem_u32(const void* p) {
    u32 a; asm("{ .reg .u64 t; cvta.to.shared.u64 t, %1; cvt.u32.u64 %0, t; }" : "=r"(a) : "l"(p));
    return a;
}
__device__ __forceinline__ void cp16(u32 dst, const void* src, int srcsize) {
    asm volatile("cp.async.cg.shared.global [%0], [%1], 16, %2;"
                 :: "r"(dst), "l"(src), "r"(srcsize) : "memory");
}
__device__ __forceinline__ void cp_commit() {
    asm volatile("cp.async.commit_group;" ::: "memory");
}
__device__ __forceinline__ void cp_wait2() {
    asm volatile("cp.async.wait_group 2;" ::: "memory");
}
__device__ __forceinline__ float4 lds128(u32 addr) {
    float4 v;
    asm volatile("ld.shared.v4.f32 {%0,%1,%2,%3}, [%4];"
                 : "=f"(v.x), "=f"(v.y), "=f"(v.z), "=f"(v.w) : "r"(addr));
    return v;
}

#define MMA_TF32(d, a0, a1, a2, a3, b0, b1)                                     \
    asm volatile("mma.sync.aligned.m16n8k8.row.col.f32.tf32.tf32.f32 "          \
                 "{%0,%1,%2,%3}, {%4,%5,%6,%7}, {%8,%9}, {%0,%1,%2,%3};"        \
                 : "+f"(d[0]), "+f"(d[1]), "+f"(d[2]), "+f"(d[3])               \
                 : "r"(a0), "r"(a1), "r"(a2), "r"(a3), "r"(b0), "r"(b1))

// ---------------------------------------------------------------------------
// Weight prep (tf32 rounded, fragment-pair packed).
// ---------------------------------------------------------------------------
__global__ void prep_weights(const float* __restrict__ W, float* __restrict__ dst) {
    int k = blockIdx.x;
    int t = threadIdx.x;                 // 0..255
    int lane = t & 31, ntp = (t >> 5) & 1, kt = t >> 6;
    int r   = lane >> 2;
    int ci0 = (lane & 3) * 8 + kt * 2 + 0;
    int ci1 = (lane & 3) * 8 + kt * 2 + 1;
    int co0 = (2 * ntp) * 8 + r;
    int co1 = (2 * ntp + 1) * 8 + r;
    float4 w4;
    w4.x = __uint_as_float(tf32_rna(W[k * 1024 + ci0 * 32 + co0]));
    w4.y = __uint_as_float(tf32_rna(W[k * 1024 + ci1 * 32 + co0]));
    w4.z = __uint_as_float(tf32_rna(W[k * 1024 + ci0 * 32 + co1]));
    w4.w = __uint_as_float(tf32_rna(W[k * 1024 + ci1 * 32 + co1]));
    ((float4*)dst)[k * 256 + t] = w4;
}

// ---------------------------------------------------------------------------
// Elementwise tf32 rounding pass (first layer's input).
// ---------------------------------------------------------------------------
__global__ __launch_bounds__(256)
void cvt_tf32_kernel(const float* __restrict__ x, float* __restrict__ y, int total4)
{
    for (int i = blockIdx.x * blockDim.x + threadIdx.x; i < total4;
         i += gridDim.x * blockDim.x) {
        float4 v = ((const float4*)x)[i];
        v.x = __uint_as_float(tf32_rna(v.x));
        v.y = __uint_as_float(tf32_rna(v.y));
        v.z = __uint_as_float(tf32_rna(v.z));
        v.w = __uint_as_float(tf32_rna(v.w));
        ((float4*)y)[i] = v;
    }
}

// ---------------------------------------------------------------------------
// Issue the 4 cp.asyncs for one offset into a ring stage (lane-private bytes).
// ---------------------------------------------------------------------------
__device__ __forceinline__ void issue_gather(u32 sbase, const float* __restrict__ in,
                                             int idx_next, int gid, int tg)
{
    const int iA = __shfl_sync(0xffffffffu, idx_next, gid);
    const int iB = __shfl_sync(0xffffffffu, idx_next, 8 + gid);
    const u32 dA = sbase + gid * ROWPITCH + tg * 32;
    const u32 dB = sbase + (8 + gid) * ROWPITCH + tg * 32;
    const char* pA = (const char*)(in + (size_t)(iA < 0 ? 0 : iA) * 32) + tg * 32;
    const char* pB = (const char*)(in + (size_t)(iB < 0 ? 0 : iB) * 32) + tg * 32;
    const int szA = (iA >= 0) ? 16 : 0;
    const int szB = (iB >= 0) ? 16 : 0;
    cp16(dA,      pA,      szA);
    cp16(dA + 16, pA + 16, szA);
    cp16(dB,      pB,      szB);
    cp16(dB + 16, pB + 16, szB);
}

// ---------------------------------------------------------------------------
// conv: block = 256 threads (8 warps), tile = 128 voxels x 32 out-channels.
// ---------------------------------------------------------------------------
template<int KVOL>
__global__ __launch_bounds__(256, 3)
void conv_mma(const float* __restrict__ in, const int* __restrict__ nmap,
              const float* __restrict__ Wp, float* __restrict__ out,
              float* __restrict__ stats, int N)
{
    extern __shared__ char ring_raw[];
    __shared__ float Red[8 * 64];

    const int tid  = threadIdx.x;
    const int wid  = tid >> 5, lane = tid & 31;
    const int gid  = lane >> 2, tg = lane & 3;
    const int mbase = blockIdx.x * 128;
    const int mrow  = mbase + wid * 16 + (lane & 15);
    const bool mv   = (mrow < N);

    const u32 ring = smem_u32(ring_raw) + wid * (STAGES * WSTAGE);

    float acc[4][4];
#pragma unroll
    for (int nt = 0; nt < 4; ++nt)
#pragma unroll
        for (int j = 0; j < 4; ++j) acc[nt][j] = 0.f;

    // ---- prologue: fill stages 0..STAGES-2 ----
    int idx_next = mv ? __ldg(nmap + mrow) : -1;
#pragma unroll
    for (int s = 0; s < STAGES - 1; ++s) {
        if (s < KVOL) issue_gather(ring + s * WSTAGE, in, idx_next, gid, tg);
        cp_commit();
        idx_next = (s + 1 < KVOL && mv) ? __ldg(nmap + (size_t)(s + 1) * N + mrow) : -1;
    }
    // idx_next now holds the index for offset STAGES-1

#pragma unroll
    for (int k = 0; k < KVOL; ++k) {
        // issue gather for k+STAGES-1
        const int ks = k + STAGES - 1;
        if (ks < KVOL)
            issue_gather(ring + (ks % STAGES) * WSTAGE, in, idx_next, gid, tg);
        cp_commit();
        idx_next = (ks + 1 < KVOL && mv) ? __ldg(nmap + (size_t)(ks + 1) * N + mrow) : -1;

        // stage k ready after <=2 pending groups remain
        cp_wait2();
        const u32 sb = ring + (k % STAGES) * WSTAGE;
        const u32 aA = sb + gid * ROWPITCH + tg * 32;
        const u32 aB = sb + (8 + gid) * ROWPITCH + tg * 32;
        float4 c0 = lds128(aA), c1 = lds128(aA + 16);
        float4 c2 = lds128(aB), c3 = lds128(aB + 16);

        u32 A0[4] = { __float_as_uint(c0.x), __float_as_uint(c0.z), __float_as_uint(c1.x), __float_as_uint(c1.z) };
        u32 A2[4] = { __float_as_uint(c0.y), __float_as_uint(c0.w), __float_as_uint(c1.y), __float_as_uint(c1.w) };
        u32 A1[4] = { __float_as_uint(c2.x), __float_as_uint(c2.z), __float_as_uint(c3.x), __float_as_uint(c3.z) };
        u32 A3[4] = { __float_as_uint(c2.y), __float_as_uint(c2.w), __float_as_uint(c3.y), __float_as_uint(c3.w) };

        const float4* wb = (const float4*)Wp + (size_t)k * 256 + lane;
#pragma unroll
        for (int kt = 0; kt < 4; ++kt) {
#pragma unroll
            for (int ntp = 0; ntp < 2; ++ntp) {
                float4 w = __ldg(wb + kt * 64 + ntp * 32);
                u32 b00 = __float_as_uint(w.x), b01 = __float_as_uint(w.y);
                u32 b10 = __float_as_uint(w.z), b11 = __float_as_uint(w.w);
                MMA_TF32(acc[2 * ntp + 0], A0[kt], A1[kt], A2[kt], A3[kt], b00, b01);
                MMA_TF32(acc[2 * ntp + 1], A0[kt], A1[kt], A2[kt], A3[kt], b10, b11);
            }
        }
    }

    // ---- epilogue: store + fused BN stats ----
    const int r0 = mbase + wid * 16 + gid;
    const int r1 = r0 + 8;
#pragma unroll
    for (int nt = 0; nt < 4; ++nt) {
        int c = nt * 8 + tg * 2;
        if (r0 < N) *(float2*)(out + (size_t)r0 * 32 + c) = make_float2(acc[nt][0], acc[nt][1]);
        if (r1 < N) *(float2*)(out + (size_t)r1 * 32 + c) = make_float2(acc[nt][2], acc[nt][3]);
    }

    float s[4][2], q[4][2];
#pragma unroll
    for (int nt = 0; nt < 4; ++nt)
#pragma unroll
        for (int j = 0; j < 2; ++j) {
            float v0 = acc[nt][j], v1 = acc[nt][2 + j];
            s[nt][j] = v0 + v1;
            q[nt][j] = v0 * v0 + v1 * v1;
        }
#pragma unroll
    for (int off = 4; off < 32; off <<= 1)
#pragma unroll
        for (int nt = 0; nt < 4; ++nt)
#pragma unroll
            for (int j = 0; j < 2; ++j) {
                s[nt][j] += __shfl_xor_sync(0xffffffffu, s[nt][j], off);
                q[nt][j] += __shfl_xor_sync(0xffffffffu, q[nt][j], off);
            }
    if (lane < 4) {
#pragma unroll
        for (int nt = 0; nt < 4; ++nt)
#pragma unroll
            for (int j = 0; j < 2; ++j) {
                int c = nt * 8 + tg * 2 + j;
                Red[wid * 64 + c]      = s[nt][j];
                Red[wid * 64 + 32 + c] = q[nt][j];
            }
    }
    __syncthreads();
    if (tid < 64) {
        int plane = tid >> 5, c = tid & 31;
        float v = 0.f;
#pragma unroll
        for (int i = 0; i < 8; ++i) v += Red[i * 64 + plane * 32 + c];
        atomicAdd(stats + plane * 32 + c, v);
    }
}

// ---------------------------------------------------------------------------
// BN + ELU. round_tf32 != 0 -> output rounded to tf32 for the next conv.
// ---------------------------------------------------------------------------
__global__ __launch_bounds__(256)
void bnelu_kernel(const float* __restrict__ x, float* __restrict__ y,
                  const float* __restrict__ stats,
                  const float* __restrict__ gamma, const float* __restrict__ beta,
                  int N, int round_tf32)
{
    __shared__ float sc[32], sh[32];
    if (threadIdx.x < 32) {
        int c = threadIdx.x;
        float inv  = 1.0f / (float)N;
        float mean = stats[c] * inv;
        float var  = stats[32 + c] * inv - mean * mean;
        float sfac = rsqrtf(var + EPS) * gamma[c];
        sc[c] = sfac;
        sh[c] = beta[c] - mean * sfac;
    }
    __syncthreads();
    const int total4 = N * 8;
    for (int i = blockIdx.x * blockDim.x + threadIdx.x; i < total4;
         i += gridDim.x * blockDim.x) {
        float4 v = ((const float4*)x)[i];
        int c = (i * 4) & 31;
        float z;
        z = v.x * sc[c + 0] + sh[c + 0]; v.x = (z > 0.f) ? z : expm1f(z);
        z = v.y * sc[c + 1] + sh[c + 1]; v.y = (z > 0.f) ? z : expm1f(z);
        z = v.z * sc[c + 2] + sh[c + 2]; v.z = (z > 0.f) ? z : expm1f(z);
        z = v.w * sc[c + 3] + sh[c + 3]; v.w = (z > 0.f) ? z : expm1f(z);
        if (round_tf32) {
            v.x = __uint_as_float(tf32_rna(v.x));
            v.y = __uint_as_float(tf32_rna(v.y));
            v.z = __uint_as_float(tf32_rna(v.z));
            v.w = __uint_as_float(tf32_rna(v.w));
        }
        ((float4*)y)[i] = v;
    }
}

// ---------------------------------------------------------------------------
extern "C" void kernel_launch(void* const* d_in, const int* in_sizes, int n_in,
                              void* d_out, int out_size)
{
    const float* feats = (const float*)d_in[0];
    const float* W1    = (const float*)d_in[1];
    const float* g1    = (const float*)d_in[2];
    const float* b1    = (const float*)d_in[3];
    const float* W2    = (const float*)d_in[4];
    const float* g2    = (const float*)d_in[5];
    const float* b2    = (const float*)d_in[6];
    const float* W3    = (const float*)d_in[7];
    const float* g3    = (const float*)d_in[8];
    const float* b3    = (const float*)d_in[9];
    const int*   nmap3 = (const int*)d_in[10];
    const int*   nmap2 = (const int*)d_in[11];

    const int N = in_sizes[0] / 32;
    const int ntiles = (N + 127) / 128;

    float *bufA, *bufB, *bufC, *stats, *Wp;
    cudaGetSymbolAddress((void**)&bufA,  g_bufA);
    cudaGetSymbolAddress((void**)&bufB,  g_bufB);
    cudaGetSymbolAddress((void**)&bufC,  g_bufC);
    cudaGetSymbolAddress((void**)&stats, g_stats);
    cudaGetSymbolAddress((void**)&Wp,    g_Wp);

    cudaFuncSetAttribute(conv_mma<27>, cudaFuncAttributeMaxDynamicSharedMemorySize, RING_BYTES);
    cudaFuncSetAttribute(conv_mma<8>,  cudaFuncAttributeMaxDynamicSharedMemorySize, RING_BYTES);

    cudaMemsetAsync(stats, 0, 3 * 64 * sizeof(float), 0);
    prep_weights<<<27, 256>>>(W1, Wp + 0 * 1024);
    prep_weights<<< 8, 256>>>(W2, Wp + 27 * 1024);
    prep_weights<<<27, 256>>>(W3, Wp + 35 * 1024);
    cvt_tf32_kernel<<<1024, 256>>>(feats, bufC, N * 8);

    conv_mma<27><<<ntiles, 256, RING_BYTES>>>(bufC, nmap3, Wp + 0 * 1024, bufA, stats + 0, N);
    bnelu_kernel<<<2048, 256>>>(bufA, bufA, stats + 0, g1, b1, N, 1);

    conv_mma<8><<<ntiles, 256, RING_BYTES>>>(bufA, nmap2, Wp + 27 * 1024, bufB, stats + 64, N);
    bnelu_kernel<<<2048, 256>>>(bufB, bufB, stats + 64, g2, b2, N, 1);

    conv_mma<27><<<ntiles, 256, RING_BYTES>>>(bufB, nmap3, Wp + 35 * 1024, bufA, stats + 128, N);
    bnelu_kernel<<<2048, 256>>>(bufA, (float*)d_out, stats + 128, g3, b3, N, 0);
}

// round 8
// speedup vs baseline: 1.8498x; 1.8498x over previous
#include <cuda_runtime.h>
#include <cuda_fp16.h>
#include <math.h>
#include <stdint.h>

// ---------------------------------------------------------------------------
// CompletionNet via warp-level fp16 mma.sync (m16n8k16, fp32 accum),
// register-direct fragment gather with distance-2 software pipelining.
// - Activations stored fp16 in PERMUTED fragment layout by their producer
//   (cvt pass for feats, fused into bnelu between layers): each lane's
//   A-fragment halves are one contiguous 16B quarter of the 64B row.
//   gather = 2x LDG.128 per lane per offset (4 lanes cover a row: coalesced).
// - W prepacked per k as 128 float4 fragment groups (fp16 pairs).
// - Warp tile M=16 (block tile 128 voxels), 3 blocks/SM, prefetch 2 offsets
//   ahead in registers (no smem, no syncs in the main loop).
// - BN stats fused into conv epilogue (fp32); conv out is fp32.
// Logical->physical channel permutation (applied by producers and W prep):
//   c: chunk=c>>4, tg=(c&7)>>1, lo=c&1, hi=(c>>3)&1
//   phys = tg*8 + chunk*4 + hi*2 + lo
// ---------------------------------------------------------------------------

#define NMAX 500000
#define EPS  1e-5f

__device__ __half g_hbuf[NMAX * 32];   // permuted fp16 activations
__device__ float  g_F[NMAX * 32];      // fp32 conv output
__device__ float  g_stats[3 * 64];     // per layer: sum[32], sumsq[32]
__device__ float4 g_Wp[62 * 128];      // per k: 128 float4 fragment groups

typedef unsigned int u32;

__device__ __forceinline__ u32 pack_h2(float lo, float hi) {
    u32 r; asm("cvt.rn.f16x2.f32 %0, %1, %2;" : "=r"(r) : "f"(hi), "f"(lo)); return r;
}

#define MMA_F16(d, a0, a1, a2, a3, b0, b1)                                      \
    asm volatile("mma.sync.aligned.m16n8k16.row.col.f32.f16.f16.f32 "           \
                 "{%0,%1,%2,%3}, {%4,%5,%6,%7}, {%8,%9}, {%0,%1,%2,%3};"        \
                 : "+f"(d[0]), "+f"(d[1]), "+f"(d[2]), "+f"(d[3])               \
                 : "r"(a0), "r"(a1), "r"(a2), "r"(a3), "r"(b0), "r"(b1))

// ---------------------------------------------------------------------------
// Weight prep: fp16, fragment-group packed.
// Thread t = kc*64 + ntp*32 + lane writes float4 (4x half2):
//   { b0(nt=2ntp), b1(nt=2ntp), b0(nt=2ntp+1), b1(nt=2ntp+1) }
// b0(nt) = {W[kc*16+cL][co], W[kc*16+cL+1][co]},  cL=(lane&3)*2, co=nt*8+lane/4
// b1(nt) = same with +8 on the k rows.
// ---------------------------------------------------------------------------
__global__ void prep_weights(const float* __restrict__ W, float4* __restrict__ dst) {
    int k = blockIdx.x;
    int t = threadIdx.x;                 // 0..127
    int lane = t & 31, ntp = (t >> 5) & 1, kc = t >> 6;
    int r  = lane >> 2;
    int cL = (lane & 3) * 2;
    int co0 = (2 * ntp) * 8 + r;
    int co1 = co0 + 8;
    const float* Wk = W + k * 1024 + kc * 16 * 32;
    u32 p0 = pack_h2(Wk[(cL + 0) * 32 + co0], Wk[(cL + 1) * 32 + co0]);
    u32 p1 = pack_h2(Wk[(cL + 8) * 32 + co0], Wk[(cL + 9) * 32 + co0]);
    u32 p2 = pack_h2(Wk[(cL + 0) * 32 + co1], Wk[(cL + 1) * 32 + co1]);
    u32 p3 = pack_h2(Wk[(cL + 8) * 32 + co1], Wk[(cL + 9) * 32 + co1]);
    float4 v;
    v.x = __uint_as_float(p0); v.y = __uint_as_float(p1);
    v.z = __uint_as_float(p2); v.w = __uint_as_float(p3);
    dst[k * 128 + kc * 64 + ntp * 32 + lane] = v;
}

// ---------------------------------------------------------------------------
// feats fp32 -> permuted fp16. Thread per (row, tg quarter).
// Quarter tg holds logical channels {tg*2,tg*2+1, +8,+9, +16,+17, +24,+25}.
// ---------------------------------------------------------------------------
__global__ __launch_bounds__(256)
void cvt_half_kernel(const float* __restrict__ x, __half* __restrict__ y, int N)
{
    int i = blockIdx.x * blockDim.x + threadIdx.x;
    int row = i >> 2, tg = i & 3;
    if (row >= N) return;
    const float2* src = (const float2*)(x + (size_t)row * 32);
    float2 v0 = __ldg(src + tg);            // c = tg*2, tg*2+1
    float2 v1 = __ldg(src + tg + 4);        // +8
    float2 v2 = __ldg(src + tg + 8);        // +16
    float2 v3 = __ldg(src + tg + 12);       // +24
    uint4 o;
    o.x = pack_h2(v0.x, v0.y);
    o.y = pack_h2(v1.x, v1.y);
    o.z = pack_h2(v2.x, v2.y);
    o.w = pack_h2(v3.x, v3.y);
    ((uint4*)y)[(size_t)row * 4 + tg] = o;
}

// ---------------------------------------------------------------------------
// gather one row-pair quarter as two uint4 (zero for idx<0)
// ---------------------------------------------------------------------------
__device__ __forceinline__ void gather_q(uint4& a, uint4& b,
                                         const __half* __restrict__ in,
                                         int idx, int gid, int tg)
{
    const int iA = __shfl_sync(0xffffffffu, idx, gid);
    const int iB = __shfl_sync(0xffffffffu, idx, 8 + gid);
    a = make_uint4(0u, 0u, 0u, 0u); b = a;
    if (iA >= 0) a = __ldg((const uint4*)(in + (size_t)iA * 32) + tg);
    if (iB >= 0) b = __ldg((const uint4*)(in + (size_t)iB * 32) + tg);
}

// ---------------------------------------------------------------------------
// conv: block = 256 threads (8 warps), tile = 128 voxels x 32 out-channels.
// Distance-2 register prefetch of the gathered fragments.
// ---------------------------------------------------------------------------
template<int KVOL>
__global__ __launch_bounds__(256, 3)
void conv_mma(const __half* __restrict__ in, const int* __restrict__ nmap,
              const float4* __restrict__ Wp, float* __restrict__ out,
              float* __restrict__ stats, int N)
{
    __shared__ float Red[8 * 64];

    const int tid  = threadIdx.x;
    const int wid  = tid >> 5, lane = tid & 31;
    const int gid  = lane >> 2, tg = lane & 3;
    const int mbase = blockIdx.x * 128;
    const int mrow  = mbase + wid * 16 + (lane & 15);
    const bool mv   = (mrow < N);

    float acc[4][4];
#pragma unroll
    for (int nt = 0; nt < 4; ++nt)
#pragma unroll
        for (int j = 0; j < 4; ++j) acc[nt][j] = 0.f;

    // ---- prologue: prime 2 stages ----
    int idx0 = mv ? __ldg(nmap + mrow) : -1;
    uint4 cA, cB;
    gather_q(cA, cB, in, idx0, gid, tg);
    int idx1 = (KVOL > 1 && mv) ? __ldg(nmap + (size_t)N + mrow) : -1;
    uint4 nA = make_uint4(0,0,0,0), nB = nA;
    if (KVOL > 1) gather_q(nA, nB, in, idx1, gid, tg);
    int idx2 = (KVOL > 2 && mv) ? __ldg(nmap + (size_t)2 * N + mrow) : -1;

#pragma unroll
    for (int k = 0; k < KVOL; ++k) {
        // issue gather for k+2 (covers ~2 iterations of MMA work)
        uint4 pA = make_uint4(0,0,0,0), pB = pA;
        if (k + 2 < KVOL) gather_q(pA, pB, in, idx2, gid, tg);
        idx2 = (k + 3 < KVOL && mv) ? __ldg(nmap + (size_t)(k + 3) * N + mrow) : -1;

        // MMAs on current buffers: chunk0 regs (x,y), chunk1 regs (z,w)
        const float4* wb = Wp + (size_t)k * 128 + lane;
#pragma unroll
        for (int ntp = 0; ntp < 2; ++ntp) {
            float4 w0 = __ldg(wb + ntp * 32);          // kc = 0
            float4 w1 = __ldg(wb + 64 + ntp * 32);     // kc = 1
            MMA_F16(acc[2 * ntp + 0], cA.x, cB.x, cA.y, cB.y,
                    __float_as_uint(w0.x), __float_as_uint(w0.y));
            MMA_F16(acc[2 * ntp + 1], cA.x, cB.x, cA.y, cB.y,
                    __float_as_uint(w0.z), __float_as_uint(w0.w));
            MMA_F16(acc[2 * ntp + 0], cA.z, cB.z, cA.w, cB.w,
                    __float_as_uint(w1.x), __float_as_uint(w1.y));
            MMA_F16(acc[2 * ntp + 1], cA.z, cB.z, cA.w, cB.w,
                    __float_as_uint(w1.z), __float_as_uint(w1.w));
        }
        cA = nA; cB = nB; nA = pA; nB = pB;
    }

    // ---- epilogue: store fp32 + fused BN stats ----
    const int r0 = mbase + wid * 16 + gid;
    const int r1 = r0 + 8;
#pragma unroll
    for (int nt = 0; nt < 4; ++nt) {
        int c = nt * 8 + tg * 2;
        if (r0 < N) *(float2*)(out + (size_t)r0 * 32 + c) = make_float2(acc[nt][0], acc[nt][1]);
        if (r1 < N) *(float2*)(out + (size_t)r1 * 32 + c) = make_float2(acc[nt][2], acc[nt][3]);
    }

    float s[4][2], q[4][2];
#pragma unroll
    for (int nt = 0; nt < 4; ++nt)
#pragma unroll
        for (int j = 0; j < 2; ++j) {
            float v0 = acc[nt][j], v1 = acc[nt][2 + j];
            s[nt][j] = v0 + v1;
            q[nt][j] = v0 * v0 + v1 * v1;
        }
#pragma unroll
    for (int off = 4; off < 32; off <<= 1)
#pragma unroll
        for (int nt = 0; nt < 4; ++nt)
#pragma unroll
            for (int j = 0; j < 2; ++j) {
                s[nt][j] += __shfl_xor_sync(0xffffffffu, s[nt][j], off);
                q[nt][j] += __shfl_xor_sync(0xffffffffu, q[nt][j], off);
            }
    if (lane < 4) {
#pragma unroll
        for (int nt = 0; nt < 4; ++nt)
#pragma unroll
            for (int j = 0; j < 2; ++j) {
                int c = nt * 8 + tg * 2 + j;
                Red[wid * 64 + c]      = s[nt][j];
                Red[wid * 64 + 32 + c] = q[nt][j];
            }
    }
    __syncthreads();
    if (tid < 64) {
        int plane = tid >> 5, c = tid & 31;
        float v = 0.f;
#pragma unroll
        for (int i = 0; i < 8; ++i) v += Red[i * 64 + plane * 32 + c];
        atomicAdd(stats + plane * 32 + c, v);
    }
}

// ---------------------------------------------------------------------------
// BN + ELU -> permuted fp16 (feeds the next conv). Thread per (row, tg).
// ---------------------------------------------------------------------------
__global__ __launch_bounds__(256)
void bnelu_half_kernel(const float* __restrict__ x, __half* __restrict__ y,
                       const float* __restrict__ stats,
                       const float* __restrict__ gamma, const float* __restrict__ beta,
                       int N)
{
    __shared__ float sc[32], sh[32];
    if (threadIdx.x < 32) {
        int c = threadIdx.x;
        float inv  = 1.0f / (float)N;
        float mean = stats[c] * inv;
        float var  = stats[32 + c] * inv - mean * mean;
        float sfac = rsqrtf(var + EPS) * gamma[c];
        sc[c] = sfac;
        sh[c] = beta[c] - mean * sfac;
    }
    __syncthreads();

    int i = blockIdx.x * blockDim.x + threadIdx.x;
    int row = i >> 2, tg = i & 3;
    if (row >= N) return;
    const float2* src = (const float2*)(x + (size_t)row * 32);
    uint4 o;
#pragma unroll
    for (int qd = 0; qd < 4; ++qd) {
        int c = tg * 2 + qd * 8;
        float2 v = __ldg(src + tg + qd * 4);
        float z0 = v.x * sc[c] + sh[c];
        float z1 = v.y * sc[c + 1] + sh[c + 1];
        z0 = (z0 > 0.f) ? z0 : expm1f(z0);
        z1 = (z1 > 0.f) ? z1 : expm1f(z1);
        ((u32*)&o)[qd] = pack_h2(z0, z1);
    }
    ((uint4*)y)[(size_t)row * 4 + tg] = o;
}

// ---------------------------------------------------------------------------
// Final BN + ELU -> fp32 output (unpermuted).
// ---------------------------------------------------------------------------
__global__ __launch_bounds__(256)
void bnelu_f32_kernel(const float* __restrict__ x, float* __restrict__ y,
                      const float* __restrict__ stats,
                      const float* __restrict__ gamma, const float* __restrict__ beta,
                      int N)
{
    __shared__ float sc[32], sh[32];
    if (threadIdx.x < 32) {
        int c = threadIdx.x;
        float inv  = 1.0f / (float)N;
        float mean = stats[c] * inv;
        float var  = stats[32 + c] * inv - mean * mean;
        float sfac = rsqrtf(var + EPS) * gamma[c];
        sc[c] = sfac;
        sh[c] = beta[c] - mean * sfac;
    }
    __syncthreads();
    const int total4 = N * 8;
    for (int i = blockIdx.x * blockDim.x + threadIdx.x; i < total4;
         i += gridDim.x * blockDim.x) {
        float4 v = ((const float4*)x)[i];
        int c = (i * 4) & 31;
        float z;
        z = v.x * sc[c + 0] + sh[c + 0]; v.x = (z > 0.f) ? z : expm1f(z);
        z = v.y * sc[c + 1] + sh[c + 1]; v.y = (z > 0.f) ? z : expm1f(z);
        z = v.z * sc[c + 2] + sh[c + 2]; v.z = (z > 0.f) ? z : expm1f(z);
        z = v.w * sc[c + 3] + sh[c + 3]; v.w = (z > 0.f) ? z : expm1f(z);
        ((float4*)y)[i] = v;
    }
}

// ---------------------------------------------------------------------------
extern "C" void kernel_launch(void* const* d_in, const int* in_sizes, int n_in,
                              void* d_out, int out_size)
{
    const float* feats = (const float*)d_in[0];
    const float* W1    = (const float*)d_in[1];
    const float* g1    = (const float*)d_in[2];
    const float* b1    = (const float*)d_in[3];
    const float* W2    = (const float*)d_in[4];
    const float* g2    = (const float*)d_in[5];
    const float* b2    = (const float*)d_in[6];
    const float* W3    = (const float*)d_in[7];
    const float* g3    = (const float*)d_in[8];
    const float* b3    = (const float*)d_in[9];
    const int*   nmap3 = (const int*)d_in[10];
    const int*   nmap2 = (const int*)d_in[11];

    const int N = in_sizes[0] / 32;
    const int ntiles = (N + 127) / 128;
    const int nquads = (N * 4 + 255) / 256;

    __half* hA;
    float *F, *stats;
    float4* Wp;
    cudaGetSymbolAddress((void**)&hA,    g_hbuf);
    cudaGetSymbolAddress((void**)&F,     g_F);
    cudaGetSymbolAddress((void**)&stats, g_stats);
    cudaGetSymbolAddress((void**)&Wp,    g_Wp);

    cudaMemsetAsync(stats, 0, 3 * 64 * sizeof(float), 0);
    prep_weights<<<27, 128>>>(W1, Wp + 0 * 128);
    prep_weights<<< 8, 128>>>(W2, Wp + 27 * 128);
    prep_weights<<<27, 128>>>(W3, Wp + 35 * 128);
    cvt_half_kernel<<<nquads, 256>>>(feats, hA, N);

    conv_mma<27><<<ntiles, 256>>>(hA, nmap3, Wp + 0 * 128, F, stats + 0, N);
    bnelu_half_kernel<<<nquads, 256>>>(F, hA, stats + 0, g1, b1, N);

    conv_mma<8><<<ntiles, 256>>>(hA, nmap2, Wp + 27 * 128, F, stats + 64, N);
    bnelu_half_kernel<<<nquads, 256>>>(F, hA, stats + 64, g2, b2, N);

    conv_mma<27><<<ntiles, 256>>>(hA, nmap3, Wp + 35 * 128, F, stats + 128, N);
    bnelu_f32_kernel<<<2048, 256>>>(F, (float*)d_out, stats + 128, g3, b3, N);
}

// round 9
// speedup vs baseline: 2.1264x; 1.1495x over previous
#include <cuda_runtime.h>
#include <cuda_fp16.h>
#include <math.h>
#include <stdint.h>

// ---------------------------------------------------------------------------
// CompletionNet via warp-level fp16 mma.sync (m16n8k16, fp32 accum).
// M=32 warp tile (block tile 256 voxels), register-direct fragment gather,
// distance-2 software pipelining (3 rolling register stages).
// - Activations stored fp16 in PERMUTED fragment layout by their producer:
//   each lane's A-fragment halves are one contiguous 16B quarter of the
//   64B row -> gather = 4x LDG.128 per lane per offset, fully coalesced.
// - W prepacked per k as 128 float4 fragment groups (fp16 pairs).
// - BN stats fused into conv epilogue (fp32); conv out fp32.
// Logical->physical channel permutation (producers + W prep):
//   phys = tg*8 + chunk*4 + hi*2 + lo  for  c = chunk*16 + hi*8 + tg*2 + lo
// ---------------------------------------------------------------------------

#define NMAX 500000
#define EPS  1e-5f

__device__ __half g_hbuf[NMAX * 32];   // permuted fp16 activations
__device__ float  g_F[NMAX * 32];      // fp32 conv output
__device__ float  g_stats[3 * 64];     // per layer: sum[32], sumsq[32]
__device__ float4 g_Wp[62 * 128];      // per k: 128 float4 fragment groups

typedef unsigned int u32;

__device__ __forceinline__ u32 pack_h2(float lo, float hi) {
    u32 r; asm("cvt.rn.f16x2.f32 %0, %1, %2;" : "=r"(r) : "f"(hi), "f"(lo)); return r;
}

#define MMA_F16(d, a0, a1, a2, a3, b0, b1)                                      \
    asm volatile("mma.sync.aligned.m16n8k16.row.col.f32.f16.f16.f32 "           \
                 "{%0,%1,%2,%3}, {%4,%5,%6,%7}, {%8,%9}, {%0,%1,%2,%3};"        \
                 : "+f"(d[0]), "+f"(d[1]), "+f"(d[2]), "+f"(d[3])               \
                 : "r"(a0), "r"(a1), "r"(a2), "r"(a3), "r"(b0), "r"(b1))

// ---------------------------------------------------------------------------
// Weight prep: fp16, fragment-group packed (same as R8).
// ---------------------------------------------------------------------------
__global__ void prep_weights(const float* __restrict__ W, float4* __restrict__ dst) {
    int k = blockIdx.x;
    int t = threadIdx.x;                 // 0..127
    int lane = t & 31, ntp = (t >> 5) & 1, kc = t >> 6;
    int r  = lane >> 2;
    int cL = (lane & 3) * 2;
    int co0 = (2 * ntp) * 8 + r;
    int co1 = co0 + 8;
    const float* Wk = W + k * 1024 + kc * 16 * 32;
    u32 p0 = pack_h2(Wk[(cL + 0) * 32 + co0], Wk[(cL + 1) * 32 + co0]);
    u32 p1 = pack_h2(Wk[(cL + 8) * 32 + co0], Wk[(cL + 9) * 32 + co0]);
    u32 p2 = pack_h2(Wk[(cL + 0) * 32 + co1], Wk[(cL + 1) * 32 + co1]);
    u32 p3 = pack_h2(Wk[(cL + 8) * 32 + co1], Wk[(cL + 9) * 32 + co1]);
    float4 v;
    v.x = __uint_as_float(p0); v.y = __uint_as_float(p1);
    v.z = __uint_as_float(p2); v.w = __uint_as_float(p3);
    dst[k * 128 + kc * 64 + ntp * 32 + lane] = v;
}

// ---------------------------------------------------------------------------
// feats fp32 -> permuted fp16. Thread per (row, tg quarter).
// ---------------------------------------------------------------------------
__global__ __launch_bounds__(256)
void cvt_half_kernel(const float* __restrict__ x, __half* __restrict__ y, int N)
{
    int i = blockIdx.x * blockDim.x + threadIdx.x;
    int row = i >> 2, tg = i & 3;
    if (row >= N) return;
    const float2* src = (const float2*)(x + (size_t)row * 32);
    float2 v0 = __ldg(src + tg);
    float2 v1 = __ldg(src + tg + 4);
    float2 v2 = __ldg(src + tg + 8);
    float2 v3 = __ldg(src + tg + 12);
    uint4 o;
    o.x = pack_h2(v0.x, v0.y);
    o.y = pack_h2(v1.x, v1.y);
    o.z = pack_h2(v2.x, v2.y);
    o.w = pack_h2(v3.x, v3.y);
    ((uint4*)y)[(size_t)row * 4 + tg] = o;
}

// ---------------------------------------------------------------------------
// gather 4 row-group quarters (zero for idx<0): rows gid, 8+gid, 16+gid, 24+gid
// ---------------------------------------------------------------------------
__device__ __forceinline__ void gather4(uint4& a, uint4& b, uint4& c, uint4& d,
                                        const __half* __restrict__ in,
                                        int idx, int gid, int tg)
{
    const int iA = __shfl_sync(0xffffffffu, idx, gid);
    const int iB = __shfl_sync(0xffffffffu, idx, 8 + gid);
    const int iC = __shfl_sync(0xffffffffu, idx, 16 + gid);
    const int iD = __shfl_sync(0xffffffffu, idx, 24 + gid);
    a = make_uint4(0u, 0u, 0u, 0u); b = a; c = a; d = a;
    if (iA >= 0) a = __ldg((const uint4*)(in + (size_t)iA * 32) + tg);
    if (iB >= 0) b = __ldg((const uint4*)(in + (size_t)iB * 32) + tg);
    if (iC >= 0) c = __ldg((const uint4*)(in + (size_t)iC * 32) + tg);
    if (iD >= 0) d = __ldg((const uint4*)(in + (size_t)iD * 32) + tg);
}

// ---------------------------------------------------------------------------
// conv: block = 256 threads (8 warps), tile = 256 voxels x 32 out-channels.
// Warp tile M=32 (2 m-subtiles of 16). Distance-2 register prefetch.
// ---------------------------------------------------------------------------
template<int KVOL>
__global__ __launch_bounds__(256, 2)
void conv_mma(const __half* __restrict__ in, const int* __restrict__ nmap,
              const float4* __restrict__ Wp, float* __restrict__ out,
              float* __restrict__ stats, int N)
{
    __shared__ float Red[8 * 64];

    const int tid  = threadIdx.x;
    const int wid  = tid >> 5, lane = tid & 31;
    const int gid  = lane >> 2, tg = lane & 3;
    const int mbase = blockIdx.x * 256;
    const int mrow  = mbase + wid * 32 + lane;
    const bool mv   = (mrow < N);

    float acc[2][4][4];
#pragma unroll
    for (int mt = 0; mt < 2; ++mt)
#pragma unroll
        for (int nt = 0; nt < 4; ++nt)
#pragma unroll
            for (int j = 0; j < 4; ++j) acc[mt][nt][j] = 0.f;

    // ---- prologue: prime 2 stages ----
    int idx0 = mv ? __ldg(nmap + mrow) : -1;
    uint4 cA, cB, cC, cD;
    gather4(cA, cB, cC, cD, in, idx0, gid, tg);
    int idx1 = (KVOL > 1 && mv) ? __ldg(nmap + (size_t)N + mrow) : -1;
    uint4 nA = make_uint4(0,0,0,0), nB = nA, nC = nA, nD = nA;
    if (KVOL > 1) gather4(nA, nB, nC, nD, in, idx1, gid, tg);
    int idx2 = (KVOL > 2 && mv) ? __ldg(nmap + (size_t)2 * N + mrow) : -1;

#pragma unroll
    for (int k = 0; k < KVOL; ++k) {
        // issue gather for k+2 (flies under the 16 MMAs below)
        uint4 pA = make_uint4(0,0,0,0), pB = pA, pC = pA, pD = pA;
        if (k + 2 < KVOL) gather4(pA, pB, pC, pD, in, idx2, gid, tg);
        idx2 = (k + 3 < KVOL && mv) ? __ldg(nmap + (size_t)(k + 3) * N + mrow) : -1;

        const float4* wb = Wp + (size_t)k * 128 + lane;
#pragma unroll
        for (int ntp = 0; ntp < 2; ++ntp) {
            float4 w0 = __ldg(wb + ntp * 32);          // kc = 0
            float4 w1 = __ldg(wb + 64 + ntp * 32);     // kc = 1
            const u32 b00 = __float_as_uint(w0.x), b01 = __float_as_uint(w0.y);
            const u32 b02 = __float_as_uint(w0.z), b03 = __float_as_uint(w0.w);
            const u32 b10 = __float_as_uint(w1.x), b11 = __float_as_uint(w1.y);
            const u32 b12 = __float_as_uint(w1.z), b13 = __float_as_uint(w1.w);
            // m-subtile 0 (rows gid, 8+gid)
            MMA_F16(acc[0][2 * ntp + 0], cA.x, cB.x, cA.y, cB.y, b00, b01);
            MMA_F16(acc[0][2 * ntp + 1], cA.x, cB.x, cA.y, cB.y, b02, b03);
            MMA_F16(acc[0][2 * ntp + 0], cA.z, cB.z, cA.w, cB.w, b10, b11);
            MMA_F16(acc[0][2 * ntp + 1], cA.z, cB.z, cA.w, cB.w, b12, b13);
            // m-subtile 1 (rows 16+gid, 24+gid)
            MMA_F16(acc[1][2 * ntp + 0], cC.x, cD.x, cC.y, cD.y, b00, b01);
            MMA_F16(acc[1][2 * ntp + 1], cC.x, cD.x, cC.y, cD.y, b02, b03);
            MMA_F16(acc[1][2 * ntp + 0], cC.z, cD.z, cC.w, cD.w, b10, b11);
            MMA_F16(acc[1][2 * ntp + 1], cC.z, cD.z, cC.w, cD.w, b12, b13);
        }
        cA = nA; cB = nB; cC = nC; cD = nD;
        nA = pA; nB = pB; nC = pC; nD = pD;
    }

    // ---- epilogue: store fp32 + fused BN stats ----
#pragma unroll
    for (int mt = 0; mt < 2; ++mt) {
        const int r0 = mbase + wid * 32 + mt * 16 + gid;
        const int r1 = r0 + 8;
#pragma unroll
        for (int nt = 0; nt < 4; ++nt) {
            int c = nt * 8 + tg * 2;
            if (r0 < N) *(float2*)(out + (size_t)r0 * 32 + c) =
                make_float2(acc[mt][nt][0], acc[mt][nt][1]);
            if (r1 < N) *(float2*)(out + (size_t)r1 * 32 + c) =
                make_float2(acc[mt][nt][2], acc[mt][nt][3]);
        }
    }

    float s[4][2], q[4][2];
#pragma unroll
    for (int nt = 0; nt < 4; ++nt)
#pragma unroll
        for (int j = 0; j < 2; ++j) {
            float v0 = acc[0][nt][j], v1 = acc[0][nt][2 + j];
            float v2 = acc[1][nt][j], v3 = acc[1][nt][2 + j];
            s[nt][j] = (v0 + v1) + (v2 + v3);
            q[nt][j] = (v0 * v0 + v1 * v1) + (v2 * v2 + v3 * v3);
        }
#pragma unroll
    for (int off = 4; off < 32; off <<= 1)
#pragma unroll
        for (int nt = 0; nt < 4; ++nt)
#pragma unroll
            for (int j = 0; j < 2; ++j) {
                s[nt][j] += __shfl_xor_sync(0xffffffffu, s[nt][j], off);
                q[nt][j] += __shfl_xor_sync(0xffffffffu, q[nt][j], off);
            }
    if (lane < 4) {
#pragma unroll
        for (int nt = 0; nt < 4; ++nt)
#pragma unroll
            for (int j = 0; j < 2; ++j) {
                int c = nt * 8 + tg * 2 + j;
                Red[wid * 64 + c]      = s[nt][j];
                Red[wid * 64 + 32 + c] = q[nt][j];
            }
    }
    __syncthreads();
    if (tid < 64) {
        int plane = tid >> 5, c = tid & 31;
        float v = 0.f;
#pragma unroll
        for (int i = 0; i < 8; ++i) v += Red[i * 64 + plane * 32 + c];
        atomicAdd(stats + plane * 32 + c, v);
    }
}

// ---------------------------------------------------------------------------
// BN + ELU -> permuted fp16 (feeds the next conv). Thread per (row, tg).
// ---------------------------------------------------------------------------
__global__ __launch_bounds__(256)
void bnelu_half_kernel(const float* __restrict__ x, __half* __restrict__ y,
                       const float* __restrict__ stats,
                       const float* __restrict__ gamma, const float* __restrict__ beta,
                       int N)
{
    __shared__ float sc[32], sh[32];
    if (threadIdx.x < 32) {
        int c = threadIdx.x;
        float inv  = 1.0f / (float)N;
        float mean = stats[c] * inv;
        float var  = stats[32 + c] * inv - mean * mean;
        float sfac = rsqrtf(var + EPS) * gamma[c];
        sc[c] = sfac;
        sh[c] = beta[c] - mean * sfac;
    }
    __syncthreads();

    int i = blockIdx.x * blockDim.x + threadIdx.x;
    int row = i >> 2, tg = i & 3;
    if (row >= N) return;
    const float2* src = (const float2*)(x + (size_t)row * 32);
    uint4 o;
#pragma unroll
    for (int qd = 0; qd < 4; ++qd) {
        int c = tg * 2 + qd * 8;
        float2 v = __ldg(src + tg + qd * 4);
        float z0 = v.x * sc[c] + sh[c];
        float z1 = v.y * sc[c + 1] + sh[c + 1];
        z0 = (z0 > 0.f) ? z0 : expm1f(z0);
        z1 = (z1 > 0.f) ? z1 : expm1f(z1);
        ((u32*)&o)[qd] = pack_h2(z0, z1);
    }
    ((uint4*)y)[(size_t)row * 4 + tg] = o;
}

// ---------------------------------------------------------------------------
// Final BN + ELU -> fp32 output (unpermuted).
// ---------------------------------------------------------------------------
__global__ __launch_bounds__(256)
void bnelu_f32_kernel(const float* __restrict__ x, float* __restrict__ y,
                      const float* __restrict__ stats,
                      const float* __restrict__ gamma, const float* __restrict__ beta,
                      int N)
{
    __shared__ float sc[32], sh[32];
    if (threadIdx.x < 32) {
        int c = threadIdx.x;
        float inv  = 1.0f / (float)N;
        float mean = stats[c] * inv;
        float var  = stats[32 + c] * inv - mean * mean;
        float sfac = rsqrtf(var + EPS) * gamma[c];
        sc[c] = sfac;
        sh[c] = beta[c] - mean * sfac;
    }
    __syncthreads();
    const int total4 = N * 8;
    for (int i = blockIdx.x * blockDim.x + threadIdx.x; i < total4;
         i += gridDim.x * blockDim.x) {
        float4 v = ((const float4*)x)[i];
        int c = (i * 4) & 31;
        float z;
        z = v.x * sc[c + 0] + sh[c + 0]; v.x = (z > 0.f) ? z : expm1f(z);
        z = v.y * sc[c + 1] + sh[c + 1]; v.y = (z > 0.f) ? z : expm1f(z);
        z = v.z * sc[c + 2] + sh[c + 2]; v.z = (z > 0.f) ? z : expm1f(z);
        z = v.w * sc[c + 3] + sh[c + 3]; v.w = (z > 0.f) ? z : expm1f(z);
        ((float4*)y)[i] = v;
    }
}

// ---------------------------------------------------------------------------
extern "C" void kernel_launch(void* const* d_in, const int* in_sizes, int n_in,
                              void* d_out, int out_size)
{
    const float* feats = (const float*)d_in[0];
    const float* W1    = (const float*)d_in[1];
    const float* g1    = (const float*)d_in[2];
    const float* b1    = (const float*)d_in[3];
    const float* W2    = (const float*)d_in[4];
    const float* g2    = (const float*)d_in[5];
    const float* b2    = (const float*)d_in[6];
    const float* W3    = (const float*)d_in[7];
    const float* g3    = (const float*)d_in[8];
    const float* b3    = (const float*)d_in[9];
    const int*   nmap3 = (const int*)d_in[10];
    const int*   nmap2 = (const int*)d_in[11];

    const int N = in_sizes[0] / 32;
    const int ntiles = (N + 255) / 256;
    const int nquads = (N * 4 + 255) / 256;

    __half* hA;
    float *F, *stats;
    float4* Wp;
    cudaGetSymbolAddress((void**)&hA,    g_hbuf);
    cudaGetSymbolAddress((void**)&F,     g_F);
    cudaGetSymbolAddress((void**)&stats, g_stats);
    cudaGetSymbolAddress((void**)&Wp,    g_Wp);

    cudaMemsetAsync(stats, 0, 3 * 64 * sizeof(float), 0);
    prep_weights<<<27, 128>>>(W1, Wp + 0 * 128);
    prep_weights<<< 8, 128>>>(W2, Wp + 27 * 128);
    prep_weights<<<27, 128>>>(W3, Wp + 35 * 128);
    cvt_half_kernel<<<nquads, 256>>>(feats, hA, N);

    conv_mma<27><<<ntiles, 256>>>(hA, nmap3, Wp + 0 * 128, F, stats + 0, N);
    bnelu_half_kernel<<<nquads, 256>>>(F, hA, stats + 0, g1, b1, N);

    conv_mma<8><<<ntiles, 256>>>(hA, nmap2, Wp + 27 * 128, F, stats + 64, N);
    bnelu_half_kernel<<<nquads, 256>>>(F, hA, stats + 64, g2, b2, N);

    conv_mma<27><<<ntiles, 256>>>(hA, nmap3, Wp + 35 * 128, F, stats + 128, N);
    bnelu_f32_kernel<<<2048, 256>>>(F, (float*)d_out, stats + 128, g3, b3, N);
}

// round 10
// speedup vs baseline: 2.2098x; 1.0393x over previous
#include <cuda_runtime.h>
#include <cuda_fp16.h>
#include <math.h>
#include <stdint.h>

// ---------------------------------------------------------------------------
// CompletionNet via warp-level fp16 mma.sync (m16n8k16, fp32 accum).
// M=32 warp tile, register-direct fragment gather, distance-2 gather pipeline
// PLUS depth-5 index ring (idx loaded ~3 iterations before its shuffle/use,
// killing the shfl long-scoreboard stall identified in R9).
// Layers 1-2 write fp16 (permuted) directly from the epilogue; BN stats stay
// fp32 (from accumulators). Layer 3 writes fp32.
// Logical->physical channel permutation (producers + W prep):
//   phys quarter tg of a row holds logical channels {tg*2+1? ...}: word qd of
//   quarter tg = logical channels (tg*2 + qd*8) and (tg*2 + qd*8 + 1).
// ---------------------------------------------------------------------------

#define NMAX 500000
#define EPS  1e-5f

__device__ __half g_hA[NMAX * 32];
__device__ __half g_hB[NMAX * 32];
__device__ float  g_F[NMAX * 32];
__device__ float  g_stats[3 * 64];
__device__ float4 g_Wp[62 * 128];

typedef unsigned int u32;

__device__ __forceinline__ u32 pack_h2(float lo, float hi) {
    u32 r; asm("cvt.rn.f16x2.f32 %0, %1, %2;" : "=r"(r) : "f"(hi), "f"(lo)); return r;
}

#define MMA_F16(d, a0, a1, a2, a3, b0, b1)                                      \
    asm volatile("mma.sync.aligned.m16n8k16.row.col.f32.f16.f16.f32 "           \
                 "{%0,%1,%2,%3}, {%4,%5,%6,%7}, {%8,%9}, {%0,%1,%2,%3};"        \
                 : "+f"(d[0]), "+f"(d[1]), "+f"(d[2]), "+f"(d[3])               \
                 : "r"(a0), "r"(a1), "r"(a2), "r"(a3), "r"(b0), "r"(b1))

// ---------------------------------------------------------------------------
__global__ void prep_weights(const float* __restrict__ W, float4* __restrict__ dst) {
    int k = blockIdx.x;
    int t = threadIdx.x;                 // 0..127
    int lane = t & 31, ntp = (t >> 5) & 1, kc = t >> 6;
    int r  = lane >> 2;
    int cL = (lane & 3) * 2;
    int co0 = (2 * ntp) * 8 + r;
    int co1 = co0 + 8;
    const float* Wk = W + k * 1024 + kc * 16 * 32;
    u32 p0 = pack_h2(Wk[(cL + 0) * 32 + co0], Wk[(cL + 1) * 32 + co0]);
    u32 p1 = pack_h2(Wk[(cL + 8) * 32 + co0], Wk[(cL + 9) * 32 + co0]);
    u32 p2 = pack_h2(Wk[(cL + 0) * 32 + co1], Wk[(cL + 1) * 32 + co1]);
    u32 p3 = pack_h2(Wk[(cL + 8) * 32 + co1], Wk[(cL + 9) * 32 + co1]);
    float4 v;
    v.x = __uint_as_float(p0); v.y = __uint_as_float(p1);
    v.z = __uint_as_float(p2); v.w = __uint_as_float(p3);
    dst[k * 128 + kc * 64 + ntp * 32 + lane] = v;
}

// ---------------------------------------------------------------------------
__global__ __launch_bounds__(256)
void cvt_half_kernel(const float* __restrict__ x, __half* __restrict__ y, int N)
{
    int i = blockIdx.x * blockDim.x + threadIdx.x;
    int row = i >> 2, tg = i & 3;
    if (row >= N) return;
    const float2* src = (const float2*)(x + (size_t)row * 32);
    float2 v0 = __ldg(src + tg);
    float2 v1 = __ldg(src + tg + 4);
    float2 v2 = __ldg(src + tg + 8);
    float2 v3 = __ldg(src + tg + 12);
    uint4 o;
    o.x = pack_h2(v0.x, v0.y);
    o.y = pack_h2(v1.x, v1.y);
    o.z = pack_h2(v2.x, v2.y);
    o.w = pack_h2(v3.x, v3.y);
    ((uint4*)y)[(size_t)row * 4 + tg] = o;
}

// ---------------------------------------------------------------------------
__device__ __forceinline__ void gather4(uint4& a, uint4& b, uint4& c, uint4& d,
                                        const __half* __restrict__ in,
                                        int idx, int gid, int tg)
{
    const int iA = __shfl_sync(0xffffffffu, idx, gid);
    const int iB = __shfl_sync(0xffffffffu, idx, 8 + gid);
    const int iC = __shfl_sync(0xffffffffu, idx, 16 + gid);
    const int iD = __shfl_sync(0xffffffffu, idx, 24 + gid);
    a = make_uint4(0u, 0u, 0u, 0u); b = a; c = a; d = a;
    if (iA >= 0) a = __ldg((const uint4*)(in + (size_t)iA * 32) + tg);
    if (iB >= 0) b = __ldg((const uint4*)(in + (size_t)iB * 32) + tg);
    if (iC >= 0) c = __ldg((const uint4*)(in + (size_t)iC * 32) + tg);
    if (iD >= 0) d = __ldg((const uint4*)(in + (size_t)iD * 32) + tg);
}

// ---------------------------------------------------------------------------
// conv: block = 256 threads (8 warps), tile = 256 voxels x 32 out-channels.
// Warp tile M=32. Gather distance-2, idx ring depth 5.
// OUT_HALF: write permuted fp16 (one uint4 per row-quarter); else fp32.
// ---------------------------------------------------------------------------
template<int KVOL, bool OUT_HALF>
__global__ __launch_bounds__(256, 2)
void conv_mma(const __half* __restrict__ in, const int* __restrict__ nmap,
              const float4* __restrict__ Wp, void* __restrict__ out_v,
              float* __restrict__ stats, int N)
{
    __shared__ float Red[8 * 64];

    const int tid  = threadIdx.x;
    const int wid  = tid >> 5, lane = tid & 31;
    const int gid  = lane >> 2, tg = lane & 3;
    const int mbase = blockIdx.x * 256;
    const int mrow  = mbase + wid * 32 + lane;
    const bool mv   = (mrow < N);

    float acc[2][4][4];
#pragma unroll
    for (int mt = 0; mt < 2; ++mt)
#pragma unroll
        for (int nt = 0; nt < 4; ++nt)
#pragma unroll
            for (int j = 0; j < 4; ++j) acc[mt][nt][j] = 0.f;

    // ---- idx ring: depth 5 ----
    int idxr[5];
#pragma unroll
    for (int j = 0; j < 5; ++j)
        idxr[j] = (j < KVOL && mv) ? __ldg(nmap + (size_t)j * N + mrow) : -1;

    // ---- prime 2 gather stages ----
    uint4 cA, cB, cC, cD;
    gather4(cA, cB, cC, cD, in, idxr[0], gid, tg);
    uint4 nA = make_uint4(0,0,0,0), nB = nA, nC = nA, nD = nA;
    if (KVOL > 1) gather4(nA, nB, nC, nD, in, idxr[1], gid, tg);

#pragma unroll
    for (int k = 0; k < KVOL; ++k) {
        // gather k+2 (idx loaded 3+ iterations ago -> shfl does not stall)
        uint4 pA = make_uint4(0,0,0,0), pB = pA, pC = pA, pD = pA;
        if (k + 2 < KVOL) gather4(pA, pB, pC, pD, in, idxr[(k + 2) % 5], gid, tg);
        // refill ring slot (idx for offset k no longer needed)
        idxr[k % 5] = (k + 5 < KVOL && mv)
                    ? __ldg(nmap + (size_t)(k + 5) * N + mrow) : -1;

        const float4* wb = Wp + (size_t)k * 128 + lane;
#pragma unroll
        for (int ntp = 0; ntp < 2; ++ntp) {
            float4 w0 = __ldg(wb + ntp * 32);          // kc = 0
            float4 w1 = __ldg(wb + 64 + ntp * 32);     // kc = 1
            const u32 b00 = __float_as_uint(w0.x), b01 = __float_as_uint(w0.y);
            const u32 b02 = __float_as_uint(w0.z), b03 = __float_as_uint(w0.w);
            const u32 b10 = __float_as_uint(w1.x), b11 = __float_as_uint(w1.y);
            const u32 b12 = __float_as_uint(w1.z), b13 = __float_as_uint(w1.w);
            MMA_F16(acc[0][2 * ntp + 0], cA.x, cB.x, cA.y, cB.y, b00, b01);
            MMA_F16(acc[0][2 * ntp + 1], cA.x, cB.x, cA.y, cB.y, b02, b03);
            MMA_F16(acc[0][2 * ntp + 0], cA.z, cB.z, cA.w, cB.w, b10, b11);
            MMA_F16(acc[0][2 * ntp + 1], cA.z, cB.z, cA.w, cB.w, b12, b13);
            MMA_F16(acc[1][2 * ntp + 0], cC.x, cD.x, cC.y, cD.y, b00, b01);
            MMA_F16(acc[1][2 * ntp + 1], cC.x, cD.x, cC.y, cD.y, b02, b03);
            MMA_F16(acc[1][2 * ntp + 0], cC.z, cD.z, cC.w, cD.w, b10, b11);
            MMA_F16(acc[1][2 * ntp + 1], cC.z, cD.z, cC.w, cD.w, b12, b13);
        }
        cA = nA; cB = nB; cC = nC; cD = nD;
        nA = pA; nB = pB; nC = pC; nD = pD;
    }

    // ---- epilogue: store + fused BN stats (stats from fp32 accumulators) ----
#pragma unroll
    for (int mt = 0; mt < 2; ++mt) {
        const int r0 = mbase + wid * 32 + mt * 16 + gid;
        const int r1 = r0 + 8;
        if (OUT_HALF) {
            __half* out = (__half*)out_v;
            uint4 o0, o1;
            o0.x = pack_h2(acc[mt][0][0], acc[mt][0][1]);
            o0.y = pack_h2(acc[mt][1][0], acc[mt][1][1]);
            o0.z = pack_h2(acc[mt][2][0], acc[mt][2][1]);
            o0.w = pack_h2(acc[mt][3][0], acc[mt][3][1]);
            o1.x = pack_h2(acc[mt][0][2], acc[mt][0][3]);
            o1.y = pack_h2(acc[mt][1][2], acc[mt][1][3]);
            o1.z = pack_h2(acc[mt][2][2], acc[mt][2][3]);
            o1.w = pack_h2(acc[mt][3][2], acc[mt][3][3]);
            if (r0 < N) ((uint4*)out)[(size_t)r0 * 4 + tg] = o0;
            if (r1 < N) ((uint4*)out)[(size_t)r1 * 4 + tg] = o1;
        } else {
            float* out = (float*)out_v;
#pragma unroll
            for (int nt = 0; nt < 4; ++nt) {
                int c = nt * 8 + tg * 2;
                if (r0 < N) *(float2*)(out + (size_t)r0 * 32 + c) =
                    make_float2(acc[mt][nt][0], acc[mt][nt][1]);
                if (r1 < N) *(float2*)(out + (size_t)r1 * 32 + c) =
                    make_float2(acc[mt][nt][2], acc[mt][nt][3]);
            }
        }
    }

    float s[4][2], q[4][2];
#pragma unroll
    for (int nt = 0; nt < 4; ++nt)
#pragma unroll
        for (int j = 0; j < 2; ++j) {
            float v0 = acc[0][nt][j], v1 = acc[0][nt][2 + j];
            float v2 = acc[1][nt][j], v3 = acc[1][nt][2 + j];
            s[nt][j] = (v0 + v1) + (v2 + v3);
            q[nt][j] = (v0 * v0 + v1 * v1) + (v2 * v2 + v3 * v3);
        }
#pragma unroll
    for (int off = 4; off < 32; off <<= 1)
#pragma unroll
        for (int nt = 0; nt < 4; ++nt)
#pragma unroll
            for (int j = 0; j < 2; ++j) {
                s[nt][j] += __shfl_xor_sync(0xffffffffu, s[nt][j], off);
                q[nt][j] += __shfl_xor_sync(0xffffffffu, q[nt][j], off);
            }
    if (lane < 4) {
#pragma unroll
        for (int nt = 0; nt < 4; ++nt)
#pragma unroll
            for (int j = 0; j < 2; ++j) {
                int c = nt * 8 + tg * 2 + j;
                Red[wid * 64 + c]      = s[nt][j];
                Red[wid * 64 + 32 + c] = q[nt][j];
            }
    }
    __syncthreads();
    if (tid < 64) {
        int plane = tid >> 5, c = tid & 31;
        float v = 0.f;
#pragma unroll
        for (int i = 0; i < 8; ++i) v += Red[i * 64 + plane * 32 + c];
        atomicAdd(stats + plane * 32 + c, v);
    }
}

// ---------------------------------------------------------------------------
// BN + ELU on permuted fp16 in -> permuted fp16 out. Thread per (row, tg).
// ---------------------------------------------------------------------------
__global__ __launch_bounds__(256)
void bnelu_h2h_kernel(const __half* __restrict__ x, __half* __restrict__ y,
                      const float* __restrict__ stats,
                      const float* __restrict__ gamma, const float* __restrict__ beta,
                      int N)
{
    __shared__ float sc[32], sh[32];
    if (threadIdx.x < 32) {
        int c = threadIdx.x;
        float inv  = 1.0f / (float)N;
        float mean = stats[c] * inv;
        float var  = stats[32 + c] * inv - mean * mean;
        float sfac = rsqrtf(var + EPS) * gamma[c];
        sc[c] = sfac;
        sh[c] = beta[c] - mean * sfac;
    }
    __syncthreads();

    int i = blockIdx.x * blockDim.x + threadIdx.x;
    int row = i >> 2, tg = i & 3;
    if (row >= N) return;
    uint4 v = __ldg((const uint4*)x + (size_t)row * 4 + tg);
    uint4 o;
#pragma unroll
    for (int qd = 0; qd < 4; ++qd) {
        int c = tg * 2 + qd * 8;
        __half2 h = *(__half2*)(((u32*)&v) + qd);
        float2 f = __half22float2(h);
        float z0 = f.x * sc[c] + sh[c];
        float z1 = f.y * sc[c + 1] + sh[c + 1];
        z0 = (z0 > 0.f) ? z0 : expm1f(z0);
        z1 = (z1 > 0.f) ? z1 : expm1f(z1);
        ((u32*)&o)[qd] = pack_h2(z0, z1);
    }
    ((uint4*)y)[(size_t)row * 4 + tg] = o;
}

// ---------------------------------------------------------------------------
// Final BN + ELU: fp32 in -> fp32 out (unpermuted).
// ---------------------------------------------------------------------------
__global__ __launch_bounds__(256)
void bnelu_f32_kernel(const float* __restrict__ x, float* __restrict__ y,
                      const float* __restrict__ stats,
                      const float* __restrict__ gamma, const float* __restrict__ beta,
                      int N)
{
    __shared__ float sc[32], sh[32];
    if (threadIdx.x < 32) {
        int c = threadIdx.x;
        float inv  = 1.0f / (float)N;
        float mean = stats[c] * inv;
        float var  = stats[32 + c] * inv - mean * mean;
        float sfac = rsqrtf(var + EPS) * gamma[c];
        sc[c] = sfac;
        sh[c] = beta[c] - mean * sfac;
    }
    __syncthreads();
    const int total4 = N * 8;
    for (int i = blockIdx.x * blockDim.x + threadIdx.x; i < total4;
         i += gridDim.x * blockDim.x) {
        float4 v = ((const float4*)x)[i];
        int c = (i * 4) & 31;
        float z;
        z = v.x * sc[c + 0] + sh[c + 0]; v.x = (z > 0.f) ? z : expm1f(z);
        z = v.y * sc[c + 1] + sh[c + 1]; v.y = (z > 0.f) ? z : expm1f(z);
        z = v.z * sc[c + 2] + sh[c + 2]; v.z = (z > 0.f) ? z : expm1f(z);
        z = v.w * sc[c + 3] + sh[c + 3]; v.w = (z > 0.f) ? z : expm1f(z);
        ((float4*)y)[i] = v;
    }
}

// ---------------------------------------------------------------------------
extern "C" void kernel_launch(void* const* d_in, const int* in_sizes, int n_in,
                              void* d_out, int out_size)
{
    const float* feats = (const float*)d_in[0];
    const float* W1    = (const float*)d_in[1];
    const float* g1    = (const float*)d_in[2];
    const float* b1    = (const float*)d_in[3];
    const float* W2    = (const float*)d_in[4];
    const float* g2    = (const float*)d_in[5];
    const float* b2    = (const float*)d_in[6];
    const float* W3    = (const float*)d_in[7];
    const float* g3    = (const float*)d_in[8];
    const float* b3    = (const float*)d_in[9];
    const int*   nmap3 = (const int*)d_in[10];
    const int*   nmap2 = (const int*)d_in[11];

    const int N = in_sizes[0] / 32;
    const int ntiles = (N + 255) / 256;
    const int nquads = (N * 4 + 255) / 256;

    __half *hA, *hB;
    float *F, *stats;
    float4* Wp;
    cudaGetSymbolAddress((void**)&hA,    g_hA);
    cudaGetSymbolAddress((void**)&hB,    g_hB);
    cudaGetSymbolAddress((void**)&F,     g_F);
    cudaGetSymbolAddress((void**)&stats, g_stats);
    cudaGetSymbolAddress((void**)&Wp,    g_Wp);

    cudaMemsetAsync(stats, 0, 3 * 64 * sizeof(float), 0);
    prep_weights<<<27, 128>>>(W1, Wp + 0 * 128);
    prep_weights<<< 8, 128>>>(W2, Wp + 27 * 128);
    prep_weights<<<27, 128>>>(W3, Wp + 35 * 128);
    cvt_half_kernel<<<nquads, 256>>>(feats, hA, N);

    conv_mma<27, true><<<ntiles, 256>>>(hA, nmap3, Wp + 0 * 128, hB, stats + 0, N);
    bnelu_h2h_kernel<<<nquads, 256>>>(hB, hB, stats + 0, g1, b1, N);

    conv_mma<8, true><<<ntiles, 256>>>(hB, nmap2, Wp + 27 * 128, hA, stats + 64, N);
    bnelu_h2h_kernel<<<nquads, 256>>>(hA, hA, stats + 64, g2, b2, N);

    conv_mma<27, false><<<ntiles, 256>>>(hA, nmap3, Wp + 35 * 128, F, stats + 128, N);
    bnelu_f32_kernel<<<2048, 256>>>(F, (float*)d_out, stats + 128, g3, b3, N);
}